// round 2
// baseline (speedup 1.0000x reference)
#include <cuda_runtime.h>
#include <math.h>

#define B    64
#define T    2048
#define D    128
#define H    256
#define G4   1024
#define OUTN 64
#define MROWS (T * B)       // 131072
#define NBLK 192            // persistent grid size

// ---------------- scratch (__device__ globals; no allocation allowed) -------
__device__ float g_e[(size_t)MROWS * D];          // [t][b][d]   67 MB
__device__ float g_xg0[(size_t)MROWS * G4];       // [t][b][g]  512 MB
__device__ float g_h1all[(size_t)MROWS * H];      // [t][b][h]  128 MB
__device__ float g_logits[(size_t)MROWS * OUTN];  //             33 MB
__device__ float g_part0[8  * B * G4];            // L0 k-split partials
__device__ float g_part1[16 * B * G4];            // L1 k-split partials
__device__ float g_h0buf[2][B * H];
__device__ float g_h1buf[2][B * H];
__device__ float g_c0[B * H];
__device__ float g_c1[B * H];
__device__ float g_bias0[G4];
__device__ float g_bias1[G4];
__device__ unsigned g_bar;                        // grid barrier counter

// ---------------- helpers ----------------------------------------------------
__device__ __forceinline__ float sigf(float x) { return 1.f / (1.f + expf(-x)); }

__device__ __forceinline__ void grid_barrier(unsigned target) {
    __syncthreads();
    if (threadIdx.x == 0) {
        __threadfence();
        atomicAdd(&g_bar, 1u);
        unsigned v;
        do {
            asm volatile("ld.global.acquire.gpu.u32 %0, [%1];"
                         : "=r"(v) : "l"(&g_bar));
        } while (v < target);
        __threadfence();
    }
    __syncthreads();
}

// ---------------- tiny kernels -----------------------------------------------
__global__ void prep_bias(const float* __restrict__ bih0, const float* __restrict__ bhh0,
                          const float* __restrict__ bih1, const float* __restrict__ bhh1) {
    int i = blockIdx.x * 256 + threadIdx.x;
    if (i < G4) {
        g_bias0[i] = bih0[i] + bhh0[i];
        g_bias1[i] = bih1[i] + bhh1[i];
    }
}

// e_t[t][b][d] = (x[b][t]==0) ? 0 : table[x][d]
__global__ void embed_kernel(const int* __restrict__ x, const float* __restrict__ table) {
    size_t idx = (size_t)blockIdx.x * 256 + threadIdx.x;   // over MROWS*D
    int d = (int)(idx & (D - 1));
    size_t m = idx >> 7;                                   // m = t*64 + b
    int t = (int)(m >> 6);
    int b = (int)(m & 63);
    int xi = __ldg(&x[(size_t)b * T + t]);
    g_e[idx] = (xi == 0) ? 0.f : __ldg(&table[(size_t)xi * D + d]);
}

// ---------------- xg0 = e @ Wih0^T + bias0 : [131072 x 1024], K=128 ----------
__global__ void __launch_bounds__(256) gemm_xg0(const float* __restrict__ Wih) {
    __shared__ float As[32][132];
    __shared__ float Bs[32][132];
    const int tid = threadIdx.x;
    const int tx = tid & 15, ty = tid >> 4;          // 16x16 threads, 8x8 tiles
    const size_t m0 = (size_t)blockIdx.y * 128;
    const int    n0 = blockIdx.x * 128;

    float acc[8][8];
#pragma unroll
    for (int i = 0; i < 8; i++)
#pragma unroll
        for (int j = 0; j < 8; j++) acc[i][j] = 0.f;

    for (int kc = 0; kc < D; kc += 32) {
        for (int i = tid; i < 128 * 32; i += 256) {
            int mm = i >> 5, k = i & 31;
            As[k][mm] = g_e[(m0 + mm) * D + kc + k];
        }
        for (int i = tid; i < 128 * 32; i += 256) {
            int nn = i >> 5, k = i & 31;
            Bs[k][nn] = Wih[(size_t)(n0 + nn) * D + kc + k];
        }
        __syncthreads();
#pragma unroll
        for (int k = 0; k < 32; k++) {
            float a[8], bb[8];
#pragma unroll
            for (int i = 0; i < 8; i++) a[i] = As[k][ty * 8 + i];
#pragma unroll
            for (int j = 0; j < 8; j++) bb[j] = Bs[k][tx * 8 + j];
#pragma unroll
            for (int i = 0; i < 8; i++)
#pragma unroll
                for (int j = 0; j < 8; j++) acc[i][j] += a[i] * bb[j];
        }
        __syncthreads();
    }
#pragma unroll
    for (int i = 0; i < 8; i++) {
        size_t row = (m0 + ty * 8 + i) * G4 + n0 + tx * 8;
#pragma unroll
        for (int j = 0; j < 8; j++)
            g_xg0[row + j] = acc[i][j] + g_bias0[n0 + tx * 8 + j];
    }
}

// ---------------- persistent 2-layer LSTM recurrence -------------------------
// Phase A tile GEMM: 64(batch) x 128(gates) x 32(k) partial, 128 threads, 8x8 tiles.
__device__ __forceinline__ void small_gemm(
    float (*As)[68], float (*Bs)[132],
    const float* __restrict__ hsrc, int k0,
    const float* __restrict__ Wp,    // pre-offset: Wp[n*H + k]
    float* __restrict__ Pout,        // partial base for this kb
    int n0, int tid)
{
    const int tx = tid & 15, ty = tid >> 4;  // 16 x 8 threads
    for (int i = tid; i < 64 * 32; i += 128) {
        int m = i >> 5, k = i & 31;
        As[k][m] = hsrc[m * H + k0 + k];
    }
    for (int i = tid; i < 128 * 32; i += 128) {
        int n = i >> 5, k = i & 31;
        Bs[k][n] = Wp[(size_t)n * H + k];
    }
    __syncthreads();
    float acc[8][8];
#pragma unroll
    for (int i = 0; i < 8; i++)
#pragma unroll
        for (int j = 0; j < 8; j++) acc[i][j] = 0.f;
#pragma unroll
    for (int k = 0; k < 32; k++) {
        float a[8], bb[8];
#pragma unroll
        for (int i = 0; i < 8; i++) a[i] = As[k][ty * 8 + i];
#pragma unroll
        for (int j = 0; j < 8; j++) bb[j] = Bs[k][tx * 8 + j];
#pragma unroll
        for (int i = 0; i < 8; i++)
#pragma unroll
            for (int j = 0; j < 8; j++) acc[i][j] += a[i] * bb[j];
    }
#pragma unroll
    for (int i = 0; i < 8; i++) {
        int m = ty * 8 + i;
        float* row = Pout + (size_t)m * G4 + n0 + tx * 8;
#pragma unroll
        for (int j = 0; j < 8; j++) row[j] = acc[i][j];
    }
    __syncthreads();
}

__device__ __forceinline__ void reduce_l0(int t, int bid, int tid) {
#pragma unroll
    for (int r = 0; r < 2; r++) {
        int p = r * 8192 + bid * 128 + tid;      // 16384 (b,j) pairs
        int b = p >> 8, j = p & 255;
        const float* xg = g_xg0 + ((size_t)t * B + b) * G4;
        float gi = xg[j], gf = xg[j + 256], gg = xg[j + 512], go = xg[j + 768];
#pragma unroll
        for (int q = 0; q < 8; q++) {
            const float* P = g_part0 + (size_t)q * B * G4 + (size_t)b * G4;
            gi += P[j]; gf += P[j + 256]; gg += P[j + 512]; go += P[j + 768];
        }
        int idx = b * H + j;
        float c = sigf(gf) * g_c0[idx] + sigf(gi) * tanhf(gg);
        g_c0[idx] = c;
        g_h0buf[t & 1][idx] = sigf(go) * tanhf(c);
    }
}

__device__ __forceinline__ void reduce_l1(int tp, int lbid, int tid) {
    int p = lbid * 128 + tid;                    // 16384 threads exactly
    int b = p >> 8, j = p & 255;
    float gi = g_bias1[j], gf = g_bias1[j + 256],
          gg = g_bias1[j + 512], go = g_bias1[j + 768];
#pragma unroll
    for (int q = 0; q < 16; q++) {
        const float* P = g_part1 + (size_t)q * B * G4 + (size_t)b * G4;
        gi += P[j]; gf += P[j + 256]; gg += P[j + 512]; go += P[j + 768];
    }
    int idx = b * H + j;
    float c = sigf(gf) * g_c1[idx] + sigf(gi) * tanhf(gg);
    g_c1[idx] = c;
    float h = sigf(go) * tanhf(c);
    g_h1buf[tp & 1][idx] = h;
    g_h1all[((size_t)tp * B + b) * H + j] = h;
}

__global__ void __launch_bounds__(128, 2) lstm_kernel(
    const float* __restrict__ Whh0,
    const float* __restrict__ Wih1,
    const float* __restrict__ Whh1)
{
    __shared__ float As[32][68];
    __shared__ float Bs[32][132];
    const int bid = blockIdx.x, tid = threadIdx.x;

    // zero c0, c1, h0buf[1], h1buf[1]
    for (int i = bid * 128 + tid; i < 4 * B * H; i += NBLK * 128) {
        int a = i >> 14, r = i & 16383;
        if (a == 0)      g_c0[r] = 0.f;
        else if (a == 1) g_c1[r] = 0.f;
        else if (a == 2) g_h0buf[1][r] = 0.f;
        else             g_h1buf[1][r] = 0.f;
    }
    unsigned phase = 0;
    grid_barrier(NBLK * (++phase));

    const bool isL0 = bid < 64;
    int nb, kb;
    if (isL0) { nb = bid >> 3;        kb = bid & 7; }
    else      { int l = bid - 64; nb = l >> 4; kb = l & 15; }

    for (int t = 0; t <= T; ++t) {
        // ---- phase A: k-split partial GEMMs ----
        if (isL0) {
            if (t < T) {
                const float* hprev = g_h0buf[(t + 1) & 1];     // h0[t-1]
                small_gemm(As, Bs, hprev, kb * 32,
                           Whh0 + (size_t)nb * 128 * H + kb * 32,
                           g_part0 + (size_t)kb * B * G4, nb * 128, tid);
            }
        } else {
            if (t >= 1) {
                // layer1 step tp = t-1; K = [h0[tp] | h1[tp-1]]
                const float* src = (kb < 8) ? g_h0buf[(t - 1) & 1]   // h0[tp]
                                            : g_h1buf[t & 1];        // h1[tp-1]
                const float* W = (kb < 8) ? Wih1 : Whh1;
                int k0 = (kb & 7) * 32;
                small_gemm(As, Bs, src, k0,
                           W + (size_t)nb * 128 * H + k0,
                           g_part1 + (size_t)kb * B * G4, nb * 128, tid);
            }
        }
        grid_barrier(NBLK * (++phase));

        // ---- phase B: reduce partials + activations ----
        if (isL0) {
            if (t < T) reduce_l0(t, bid, tid);
        } else {
            if (t >= 1) reduce_l1(t - 1, bid - 64, tid);
        }
        grid_barrier(NBLK * (++phase));
    }
}

// ---------------- FC: logits = h1 @ fcW^T + fcb ; M=131072, N=64, K=256 ------
__global__ void __launch_bounds__(256) gemm_fc(const float* __restrict__ fcW,
                                               const float* __restrict__ fcb) {
    __shared__ float As[32][132];
    __shared__ float Bs[32][68];
    const int tid = threadIdx.x;
    const int tx = tid & 15, ty = tid >> 4;   // tile: 8(m) x 4(n)
    const size_t m0 = (size_t)blockIdx.x * 128;

    float acc[8][4];
#pragma unroll
    for (int i = 0; i < 8; i++)
#pragma unroll
        for (int j = 0; j < 4; j++) acc[i][j] = 0.f;

    for (int kc = 0; kc < H; kc += 32) {
        for (int i = tid; i < 128 * 32; i += 256) {
            int mm = i >> 5, k = i & 31;
            As[k][mm] = g_h1all[(m0 + mm) * H + kc + k];
        }
        for (int i = tid; i < 64 * 32; i += 256) {
            int nn = i >> 5, k = i & 31;
            Bs[k][nn] = fcW[(size_t)nn * H + kc + k];
        }
        __syncthreads();
#pragma unroll
        for (int k = 0; k < 32; k++) {
            float a[8], bb[4];
#pragma unroll
            for (int i = 0; i < 8; i++) a[i] = As[k][ty * 8 + i];
#pragma unroll
            for (int j = 0; j < 4; j++) bb[j] = Bs[k][tx * 4 + j];
#pragma unroll
            for (int i = 0; i < 8; i++)
#pragma unroll
                for (int j = 0; j < 4; j++) acc[i][j] += a[i] * bb[j];
        }
        __syncthreads();
    }
#pragma unroll
    for (int i = 0; i < 8; i++) {
        size_t row = (m0 + ty * 8 + i) * OUTN + tx * 4;
#pragma unroll
        for (int j = 0; j < 4; j++)
            g_logits[row + j] = acc[i][j] + fcb[tx * 4 + j];
    }
}

// ---------------- softmax over 64, remap [t][b] -> out[b][t] -----------------
__global__ void softmax_kernel(float* __restrict__ out) {
    const int tid = threadIdx.x;
    const int lane = tid & 31, w = tid >> 5;
    size_t row = (size_t)blockIdx.x * 8 + w;   // row = t*64 + b
    const float* L = g_logits + row * OUTN;
    float v0 = L[lane], v1 = L[lane + 32];
    float mx = fmaxf(v0, v1);
#pragma unroll
    for (int off = 16; off; off >>= 1) mx = fmaxf(mx, __shfl_xor_sync(~0u, mx, off));
    float e0 = expf(v0 - mx), e1 = expf(v1 - mx);
    float s = e0 + e1;
#pragma unroll
    for (int off = 16; off; off >>= 1) s += __shfl_xor_sync(~0u, s, off);
    float inv = 1.f / s;
    int t = (int)(row >> 6), b = (int)(row & 63);
    float* O = out + ((size_t)b * T + t) * OUTN;
    O[lane]      = e0 * inv;
    O[lane + 32] = e1 * inv;
}

// ---------------- launch ------------------------------------------------------
extern "C" void kernel_launch(void* const* d_in, const int* in_sizes, int n_in,
                              void* d_out, int out_size) {
    const int*   x     = (const int*)d_in[0];
    const float* table = (const float*)d_in[1];
    const float* Wih0  = (const float*)d_in[2];
    const float* Whh0  = (const float*)d_in[3];
    const float* bih0  = (const float*)d_in[4];
    const float* bhh0  = (const float*)d_in[5];
    const float* Wih1  = (const float*)d_in[6];
    const float* Whh1  = (const float*)d_in[7];
    const float* bih1  = (const float*)d_in[8];
    const float* bhh1  = (const float*)d_in[9];
    const float* fcW   = (const float*)d_in[10];
    const float* fcb   = (const float*)d_in[11];
    float* out = (float*)d_out;

    prep_bias<<<4, 256>>>(bih0, bhh0, bih1, bhh1);
    embed_kernel<<<(MROWS * D) / 256, 256>>>(x, table);
    gemm_xg0<<<dim3(8, MROWS / 128), 256>>>(Wih0);

    void* barAddr = nullptr;
    cudaGetSymbolAddress(&barAddr, g_bar);
    cudaMemsetAsync(barAddr, 0, sizeof(unsigned));

    lstm_kernel<<<NBLK, 128>>>(Whh0, Wih1, Whh1);

    gemm_fc<<<MROWS / 128, 256>>>(fcW, fcb);
    softmax_kernel<<<MROWS / 8, 256>>>(out);
}

// round 3
// speedup vs baseline: 2.4124x; 2.4124x over previous
#include <cuda_runtime.h>
#include <math.h>

#define B    64
#define T    2048
#define D    128
#define H    256
#define G4   1024
#define OUTN 64
#define MROWS (T * B)          // 131072
#define NB_L0 128              // layer-0 blocks (2 j each)
#define NB_L1 256              // layer-1 blocks (1 j each)
#define NBLK  (NB_L0 + NB_L1)  // 384

// ---------------- scratch ----------------------------------------------------
__device__ float g_e[(size_t)MROWS * D];           // [m][d]
__device__ float g_xg0[(size_t)MROWS * G4];        // [t][col][b]
__device__ float g_h1all[(size_t)MROWS * H];       // [t][j][b]
__device__ float g_logits[(size_t)MROWS * OUTN];   // [m][o]
__device__ float g_h0buf[2][H * B];                // [par][k][b]
__device__ float g_h1buf[2][H * B];
__device__ float g_bias0[G4];
__device__ int   g_done0[T];
__device__ int   g_done1[T];

__device__ __forceinline__ float sigf(float x) { return 1.f / (1.f + expf(-x)); }

__device__ __forceinline__ int ld_acq(const int* p) {
    int v;
    asm volatile("ld.global.acquire.gpu.b32 %0, [%1];" : "=r"(v) : "l"(p) : "memory");
    return v;
}

// ---------------- tiny kernels ------------------------------------------------
__global__ void prep_bias(const float* __restrict__ bih0, const float* __restrict__ bhh0) {
    int i = blockIdx.x * 256 + threadIdx.x;
    if (i < G4) g_bias0[i] = bih0[i] + bhh0[i];
}

__global__ void embed_kernel(const int* __restrict__ x, const float* __restrict__ table) {
    size_t idx = (size_t)blockIdx.x * 256 + threadIdx.x;    // over MROWS*D
    int d = (int)(idx & (D - 1));
    size_t m = idx >> 7;                                    // m = t*64 + b
    int t = (int)(m >> 6);
    int b = (int)(m & 63);
    int xi = __ldg(&x[(size_t)b * T + t]);
    g_e[idx] = (xi == 0) ? 0.f : __ldg(&table[(size_t)xi * D + d]);
}

// ------- xg0[t][col][b] = (e @ Wih0^T)[m][col] + bias0[col] ; K=128 ----------
__global__ void __launch_bounds__(256) gemm_xg0(const float* __restrict__ Wih) {
    __shared__ float As[32][132];
    __shared__ float Bs[32][132];
    const int tid = threadIdx.x;
    const int tx = tid & 15, ty = tid >> 4;    // tx -> m dir, ty -> n dir
    const size_t m0 = (size_t)blockIdx.y * 128;
    const int    n0 = blockIdx.x * 128;

    float acc[8][8];   // [m][n]
#pragma unroll
    for (int i = 0; i < 8; i++)
#pragma unroll
        for (int j = 0; j < 8; j++) acc[i][j] = 0.f;

    for (int kc = 0; kc < D; kc += 32) {
        for (int i = tid; i < 128 * 32; i += 256) {
            int mm = i >> 5, k = i & 31;
            As[k][mm] = g_e[(m0 + mm) * D + kc + k];
        }
        for (int i = tid; i < 128 * 32; i += 256) {
            int nn = i >> 5, k = i & 31;
            Bs[k][nn] = Wih[(size_t)(n0 + nn) * D + kc + k];
        }
        __syncthreads();
#pragma unroll
        for (int k = 0; k < 32; k++) {
            float a[8], bb[8];
#pragma unroll
            for (int i = 0; i < 8; i++) a[i] = As[k][tx * 8 + i];
#pragma unroll
            for (int j = 0; j < 8; j++) bb[j] = Bs[k][ty * 8 + j];
#pragma unroll
            for (int i = 0; i < 8; i++)
#pragma unroll
                for (int j = 0; j < 8; j++) acc[i][j] += a[i] * bb[j];
        }
        __syncthreads();
    }
    // store: m = m0 + tx*8 + i  ->  t = m>>6, b = m&63 ; out[t][col][b]
    const int tq = (int)(m0 >> 6) + (tx >> 3);      // tx<8 -> t0, tx>=8 -> t0+1
    const int bb0 = (tx & 7) * 8;
#pragma unroll
    for (int j = 0; j < 8; j++) {
        int col = n0 + ty * 8 + j;
        float bv = g_bias0[col];
        float* dst = g_xg0 + (size_t)tq * (G4 * B) + (size_t)col * B + bb0;
        float4 v0 = make_float4(acc[0][j] + bv, acc[1][j] + bv, acc[2][j] + bv, acc[3][j] + bv);
        float4 v1 = make_float4(acc[4][j] + bv, acc[5][j] + bv, acc[6][j] + bv, acc[7][j] + bv);
        *(float4*)(dst)     = v0;
        *(float4*)(dst + 4) = v1;
    }
}

// ---------------- persistent pipelined 2-layer LSTM --------------------------
__global__ void __launch_bounds__(128, 4) lstm_kernel(
    const float* __restrict__ Whh0,
    const float* __restrict__ Wih1,
    const float* __restrict__ Whh1,
    const float* __restrict__ bih1,
    const float* __restrict__ bhh1)
{
    __shared__ float w_s[2048];   // L0: [8][256]  L1: [4][512]
    __shared__ float red[2048];
    const int bid = blockIdx.x, tid = threadIdx.x;

    if (bid < NB_L0) {
        // ================= layer 0 : 2 j's, 8 gate-cols, K=256 ===============
        const int j0 = bid * 2;
        for (int i = tid; i < 8 * 256; i += 128) {
            int r = i >> 8, k = i & 255;
            int grow = (r >> 1) * 256 + j0 + (r & 1);   // gate=(r>>1), jl=(r&1)
            w_s[i] = Whh0[(size_t)grow * H + k];
        }
        const int bg = tid & 15, cg = (tid >> 4) & 1, ks = tid >> 5;  // 16x2x4
        const int b0 = bg * 4, c0 = cg * 4, kbase = ks * 64;
        const int jl = tid >> 6, ab = tid & 63;          // activation mapping
        float c_reg = 0.f;
        __syncthreads();

        for (int t = 0; t < T; ++t) {
            if (tid == 0) {
                if (t >= 1) while (ld_acq(&g_done0[t - 1]) < NB_L0) {}
                if (t >= 2) while (ld_acq(&g_done1[t - 2]) < NB_L1) {}
            }
            __syncthreads();

            const float* h = g_h0buf[(t + 1) & 1];
            float acc[4][4];
#pragma unroll
            for (int i = 0; i < 4; i++)
#pragma unroll
                for (int j = 0; j < 4; j++) acc[i][j] = 0.f;

            for (int kk = 0; kk < 64; kk += 4) {
                int k = kbase + kk;
                float hv[4][4], wv[4][4];
#pragma unroll
                for (int i = 0; i < 4; i++) {
                    float4 v = *(const float4*)(h + (size_t)(k + i) * B + b0);
                    hv[i][0] = v.x; hv[i][1] = v.y; hv[i][2] = v.z; hv[i][3] = v.w;
                }
#pragma unroll
                for (int c = 0; c < 4; c++) {
                    float4 v = *(const float4*)&w_s[(c0 + c) * 256 + k];
                    wv[c][0] = v.x; wv[c][1] = v.y; wv[c][2] = v.z; wv[c][3] = v.w;
                }
#pragma unroll
                for (int kc = 0; kc < 4; kc++)
#pragma unroll
                    for (int c = 0; c < 4; c++)
#pragma unroll
                        for (int bi = 0; bi < 4; bi++)
                            acc[bi][c] += hv[kc][bi] * wv[c][kc];
            }
#pragma unroll
            for (int c = 0; c < 4; c++)
                *(float4*)&red[ks * 512 + (c0 + c) * 64 + b0] =
                    make_float4(acc[0][c], acc[1][c], acc[2][c], acc[3][c]);
            __syncthreads();

            // activation: one (b,j) pair per thread, c-state in register
            {
                float s[4];
#pragma unroll
                for (int g = 0; g < 4; g++) {
                    int c = g * 2 + jl;
                    s[g] = red[c * 64 + ab] + red[512 + c * 64 + ab] +
                           red[1024 + c * 64 + ab] + red[1536 + c * 64 + ab];
                    s[g] += g_xg0[(size_t)t * (G4 * B) + (size_t)(g * 256 + j0 + jl) * B + ab];
                }
                c_reg = sigf(s[1]) * c_reg + sigf(s[0]) * tanhf(s[2]);
                float hval = sigf(s[3]) * tanhf(c_reg);
                g_h0buf[t & 1][(j0 + jl) * B + ab] = hval;
                __threadfence();
            }
            __syncthreads();
            if (tid == 0) atomicAdd(&g_done0[t], 1);
        }
    } else {
        // ================= layer 1 : 1 j, 4 gate-cols, K=512 =================
        const int j = bid - NB_L0;
        for (int i = tid; i < 4 * 512; i += 128) {
            int r = i >> 9, k = i & 511;
            int grow = r * 256 + j;
            w_s[i] = (k < 256) ? Wih1[(size_t)grow * H + k]
                               : Whh1[(size_t)grow * H + (k - 256)];
        }
        const int bg = tid & 15, ks = tid >> 4;          // 16 x 8
        const int b0 = bg * 4, kbase = ks * 64;
        float bi_r[4];
        if (tid < 64) {
#pragma unroll
            for (int g = 0; g < 4; g++)
                bi_r[g] = bih1[g * 256 + j] + bhh1[g * 256 + j];
        }
        float c_reg = 0.f;
        __syncthreads();

        for (int tp = 0; tp < T; ++tp) {
            if (tid == 0) {
                while (ld_acq(&g_done0[tp]) < NB_L0) {}
                if (tp >= 1) while (ld_acq(&g_done1[tp - 1]) < NB_L1) {}
            }
            __syncthreads();

            const float* hsrc = (ks < 4) ? g_h0buf[tp & 1] : g_h1buf[(tp + 1) & 1];
            const int kloc = (ks & 3) * 64;
            float acc[4][4];
#pragma unroll
            for (int i = 0; i < 4; i++)
#pragma unroll
                for (int jj = 0; jj < 4; jj++) acc[i][jj] = 0.f;

            for (int kk = 0; kk < 64; kk += 4) {
                int k = kloc + kk;
                int gk = kbase + kk;
                float hv[4][4], wv[4][4];
#pragma unroll
                for (int i = 0; i < 4; i++) {
                    float4 v = *(const float4*)(hsrc + (size_t)(k + i) * B + b0);
                    hv[i][0] = v.x; hv[i][1] = v.y; hv[i][2] = v.z; hv[i][3] = v.w;
                }
#pragma unroll
                for (int c = 0; c < 4; c++) {
                    float4 v = *(const float4*)&w_s[c * 512 + gk];
                    wv[c][0] = v.x; wv[c][1] = v.y; wv[c][2] = v.z; wv[c][3] = v.w;
                }
#pragma unroll
                for (int kc = 0; kc < 4; kc++)
#pragma unroll
                    for (int c = 0; c < 4; c++)
#pragma unroll
                        for (int bi = 0; bi < 4; bi++)
                            acc[bi][c] += hv[kc][bi] * wv[c][kc];
            }
#pragma unroll
            for (int c = 0; c < 4; c++)
                *(float4*)&red[ks * 256 + c * 64 + b0] =
                    make_float4(acc[0][c], acc[1][c], acc[2][c], acc[3][c]);
            __syncthreads();

            if (tid < 64) {
                int b = tid;
                float s[4];
#pragma unroll
                for (int g = 0; g < 4; g++) {
                    float acc2 = bi_r[g];
#pragma unroll
                    for (int q = 0; q < 8; q++) acc2 += red[q * 256 + g * 64 + b];
                    s[g] = acc2;
                }
                c_reg = sigf(s[1]) * c_reg + sigf(s[0]) * tanhf(s[2]);
                float hval = sigf(s[3]) * tanhf(c_reg);
                g_h1buf[tp & 1][j * B + b] = hval;
                g_h1all[(size_t)tp * (H * B) + j * B + b] = hval;
                __threadfence();
            }
            __syncthreads();
            if (tid == 0) atomicAdd(&g_done1[tp], 1);
        }
    }
}

// ------- FC: logits[m][o] = h1[m] . fcW[o] + fcb ; A = g_h1all[t][k][b] ------
__global__ void __launch_bounds__(256) gemm_fc(const float* __restrict__ fcW,
                                               const float* __restrict__ fcb) {
    __shared__ float As[32][132];
    __shared__ float Bs[32][68];
    const int tid = threadIdx.x;
    const int tx = tid & 15, ty = tid >> 4;
    const size_t m0 = (size_t)blockIdx.x * 128;
    const int t0 = (int)(m0 >> 6);

    float acc[8][4];
#pragma unroll
    for (int i = 0; i < 8; i++)
#pragma unroll
        for (int j = 0; j < 4; j++) acc[i][j] = 0.f;

    for (int kc = 0; kc < H; kc += 32) {
        for (int i = tid; i < 32 * 128; i += 256) {
            int k = i >> 7, mm = i & 127;
            int tq = t0 + (mm >> 6), b = mm & 63;
            As[k][mm] = g_h1all[(size_t)tq * (H * B) + (size_t)(kc + k) * B + b];
        }
        for (int i = tid; i < 64 * 32; i += 256) {
            int nn = i >> 5, k = i & 31;
            Bs[k][nn] = fcW[(size_t)nn * H + kc + k];
        }
        __syncthreads();
#pragma unroll
        for (int k = 0; k < 32; k++) {
            float a[8], bb[4];
#pragma unroll
            for (int i = 0; i < 8; i++) a[i] = As[k][ty * 8 + i];
#pragma unroll
            for (int j = 0; j < 4; j++) bb[j] = Bs[k][tx * 4 + j];
#pragma unroll
            for (int i = 0; i < 8; i++)
#pragma unroll
                for (int j = 0; j < 4; j++) acc[i][j] += a[i] * bb[j];
        }
        __syncthreads();
    }
#pragma unroll
    for (int i = 0; i < 8; i++) {
        size_t row = (m0 + ty * 8 + i) * OUTN + tx * 4;
#pragma unroll
        for (int j = 0; j < 4; j++)
            g_logits[row + j] = acc[i][j] + fcb[tx * 4 + j];
    }
}

// ---------------- softmax over 64, remap [t][b] -> out[b][t] -----------------
__global__ void softmax_kernel(float* __restrict__ out) {
    const int tid = threadIdx.x;
    const int lane = tid & 31, w = tid >> 5;
    size_t row = (size_t)blockIdx.x * 8 + w;   // row = t*64 + b
    const float* L = g_logits + row * OUTN;
    float v0 = L[lane], v1 = L[lane + 32];
    float mx = fmaxf(v0, v1);
#pragma unroll
    for (int off = 16; off; off >>= 1) mx = fmaxf(mx, __shfl_xor_sync(~0u, mx, off));
    float e0 = expf(v0 - mx), e1 = expf(v1 - mx);
    float s = e0 + e1;
#pragma unroll
    for (int off = 16; off; off >>= 1) s += __shfl_xor_sync(~0u, s, off);
    float inv = 1.f / s;
    int t = (int)(row >> 6), b = (int)(row & 63);
    float* O = out + ((size_t)b * T + t) * OUTN;
    O[lane]      = e0 * inv;
    O[lane + 32] = e1 * inv;
}

// ---------------- launch ------------------------------------------------------
extern "C" void kernel_launch(void* const* d_in, const int* in_sizes, int n_in,
                              void* d_out, int out_size) {
    const int*   x     = (const int*)d_in[0];
    const float* table = (const float*)d_in[1];
    const float* Wih0  = (const float*)d_in[2];
    const float* Whh0  = (const float*)d_in[3];
    const float* bih0  = (const float*)d_in[4];
    const float* bhh0  = (const float*)d_in[5];
    const float* Wih1  = (const float*)d_in[6];
    const float* Whh1  = (const float*)d_in[7];
    const float* bih1  = (const float*)d_in[8];
    const float* bhh1  = (const float*)d_in[9];
    const float* fcW   = (const float*)d_in[10];
    const float* fcb   = (const float*)d_in[11];
    float* out = (float*)d_out;

    // reset counters + zero-state buffers every launch (graph-capturable)
    void *p0, *p1, *ph0, *ph1;
    cudaGetSymbolAddress(&p0,  g_done0);
    cudaGetSymbolAddress(&p1,  g_done1);
    cudaGetSymbolAddress(&ph0, g_h0buf);
    cudaGetSymbolAddress(&ph1, g_h1buf);
    cudaMemsetAsync(p0,  0, T * sizeof(int));
    cudaMemsetAsync(p1,  0, T * sizeof(int));
    cudaMemsetAsync(ph0, 0, 2 * H * B * sizeof(float));
    cudaMemsetAsync(ph1, 0, 2 * H * B * sizeof(float));

    prep_bias<<<4, 256>>>(bih0, bhh0);
    embed_kernel<<<(MROWS * D) / 256, 256>>>(x, table);
    gemm_xg0<<<dim3(8, MROWS / 128), 256>>>(Wih0);

    lstm_kernel<<<NBLK, 128>>>(Whh0, Wih1, Whh1, bih1, bhh1);

    gemm_fc<<<MROWS / 128, 256>>>(fcW, fcb);
    softmax_kernel<<<MROWS / 8, 256>>>(out);
}

// round 4
// speedup vs baseline: 3.1253x; 1.2955x over previous
#include <cuda_runtime.h>
#include <math.h>

#define B    64
#define T    2048
#define D    128
#define H    256
#define G4   1024
#define OUTN 64
#define MROWS (T * B)          // 131072
#define NB_L0 128              // layer-0 blocks (2 j each)
#define NB_L1 256              // layer-1 blocks (1 j each)
#define NBLK  (NB_L0 + NB_L1)  // 384

typedef unsigned long long ull;

// ---------------- scratch ----------------------------------------------------
__device__ float g_e[(size_t)MROWS * D];           // [m][d]
__device__ float g_xg0[(size_t)MROWS * G4];        // [t][col][b]
__device__ float g_h1all[(size_t)MROWS * H];       // [t][j][b]
__device__ float g_logits[(size_t)MROWS * OUTN];   // [m][o]
__device__ float g_h0buf[4][H * B];                // [ring][k][b]
__device__ float g_h1buf[4][H * B];
__device__ float g_bias0[G4];
__device__ int   g_done0q[T][4];
__device__ int   g_done1q[T][4];

// ---------------- packed f32x2 helpers ---------------------------------------
#define FMA2(d, a, b) asm("fma.rn.f32x2 %0, %1, %2, %0;" : "+l"(d) : "l"(a), "l"(b))
#define ADD2(d, a, b) asm("add.rn.f32x2 %0, %1, %2;"     : "=l"(d) : "l"(a), "l"(b))
__device__ __forceinline__ ull dup2(float w) {
    ull d; unsigned u = __float_as_uint(w);
    asm("mov.b64 %0, {%1, %1};" : "=l"(d) : "r"(u));
    return d;
}

__device__ __forceinline__ float sigf(float x) { return 1.f / (1.f + __expf(-x)); }
__device__ __forceinline__ float tanh_f(float x) {
    float e = __expf(-2.f * fabsf(x));
    float r = (1.f - e) / (1.f + e);
    return copysignf(r, x);
}

__device__ __forceinline__ void waitq(const int* p, int thr) {
    int v;
    do {
        asm volatile("ld.global.acquire.gpu.b32 %0, [%1];" : "=r"(v) : "l"(p) : "memory");
    } while (v < thr);
}

// ---------------- tiny kernels ------------------------------------------------
__global__ void prep_bias(const float* __restrict__ bih0, const float* __restrict__ bhh0) {
    int i = blockIdx.x * 256 + threadIdx.x;
    if (i < G4) g_bias0[i] = bih0[i] + bhh0[i];
}

__global__ void embed_kernel(const int* __restrict__ x, const float* __restrict__ table) {
    size_t idx = (size_t)blockIdx.x * 256 + threadIdx.x;    // over MROWS*D
    int d = (int)(idx & (D - 1));
    size_t m = idx >> 7;                                    // m = t*64 + b
    int t = (int)(m >> 6);
    int b = (int)(m & 63);
    int xi = __ldg(&x[(size_t)b * T + t]);
    g_e[idx] = (xi == 0) ? 0.f : __ldg(&table[(size_t)xi * D + d]);
}

// ------- xg0[t][col][b] = (e @ Wih0^T)[m][col] + bias0[col] ; K=128 ----------
__global__ void __launch_bounds__(256, 2) gemm_xg0(const float* __restrict__ Wih) {
    __shared__ float As[32][132];
    __shared__ float Bs[32][132];
    const int tid = threadIdx.x;
    const int tx = tid & 15, ty = tid >> 4;    // tx -> m dir, ty -> n dir
    const size_t m0 = (size_t)blockIdx.y * 128;
    const int    n0 = blockIdx.x * 128;

    ull acc[4][8];   // [m-pair][n]
#pragma unroll
    for (int p = 0; p < 4; p++)
#pragma unroll
        for (int j = 0; j < 8; j++) acc[p][j] = 0ULL;

    for (int kc = 0; kc < D; kc += 32) {
        for (int i = tid; i < 128 * 32; i += 256) {
            int mm = i >> 5, k = i & 31;
            As[k][mm] = g_e[(m0 + mm) * D + kc + k];
        }
        for (int i = tid; i < 128 * 32; i += 256) {
            int nn = i >> 5, k = i & 31;
            Bs[k][nn] = Wih[(size_t)(n0 + nn) * D + kc + k];
        }
        __syncthreads();
#pragma unroll
        for (int k = 0; k < 32; k++) {
            ulonglong2 a01 = *(const ulonglong2*)&As[k][tx * 8];
            ulonglong2 a23 = *(const ulonglong2*)&As[k][tx * 8 + 4];
            float4 f0 = *(const float4*)&Bs[k][ty * 8];
            float4 f1 = *(const float4*)&Bs[k][ty * 8 + 4];
            ull bb[8];
            bb[0] = dup2(f0.x); bb[1] = dup2(f0.y); bb[2] = dup2(f0.z); bb[3] = dup2(f0.w);
            bb[4] = dup2(f1.x); bb[5] = dup2(f1.y); bb[6] = dup2(f1.z); bb[7] = dup2(f1.w);
#pragma unroll
            for (int j = 0; j < 8; j++) {
                FMA2(acc[0][j], a01.x, bb[j]);
                FMA2(acc[1][j], a01.y, bb[j]);
                FMA2(acc[2][j], a23.x, bb[j]);
                FMA2(acc[3][j], a23.y, bb[j]);
            }
        }
        __syncthreads();
    }
    // store: m = m0 + tx*8 + i  ->  t = m>>6, b = m&63 ; out[t][col][b]
    const int tq = (int)(m0 >> 6) + (tx >> 3);
    const int bb0 = (tx & 7) * 8;
#pragma unroll
    for (int j = 0; j < 8; j++) {
        int col = n0 + ty * 8 + j;
        ull bd = dup2(g_bias0[col]);
        ull v0, v1, v2, v3;
        ADD2(v0, acc[0][j], bd); ADD2(v1, acc[1][j], bd);
        ADD2(v2, acc[2][j], bd); ADD2(v3, acc[3][j], bd);
        float* dst = g_xg0 + ((size_t)tq * G4 + col) * B + bb0;
        ulonglong2 q0; q0.x = v0; q0.y = v1;
        ulonglong2 q1; q1.x = v2; q1.y = v3;
        *(ulonglong2*)dst       = q0;
        *(ulonglong2*)(dst + 4) = q1;
    }
}

// ---------------- persistent pipelined 2-layer LSTM --------------------------
__global__ void __launch_bounds__(128, 3) lstm_kernel(
    const float* __restrict__ Whh0,
    const float* __restrict__ Wih1,
    const float* __restrict__ Whh1,
    const float* __restrict__ bih1,
    const float* __restrict__ bhh1)
{
    __shared__ ull   w_s2[2048];   // weights pre-duplicated (w,w)
    __shared__ float red[2048];    // k-split partials
    const int bid = blockIdx.x, tid = threadIdx.x;

    if (bid < NB_L0) {
        // ========== layer 0 : 2 j's -> 8 rows (r = g*2+jl), K=256 ===========
        const int j0 = bid * 2, q0 = bid >> 5;
        for (int i = tid; i < 2048; i += 128) {
            int r = i >> 8, k = i & 255;
            float w = Whh0[(size_t)((r >> 1) * 256 + j0 + (r & 1)) * H + k];
            w_s2[i] = dup2(w);
        }
        const int bg = tid & 15, cg = (tid >> 4) & 1, ks = tid >> 5;
        const int b0 = bg * 4, kbase = ks * 64, rbase = cg * 4;
        const int ab = tid & 63, jl = tid >> 6;
        float c_reg = 0.f;
        __syncthreads();

        for (int t = 0; t < T; ++t) {
            // prefetch xg0 (DRAM) before any waiting
            const float* xgp = g_xg0 + ((size_t)t * G4 + j0 + jl) * B + ab;
            float xp0 = xgp[0];
            float xp1 = xgp[(size_t)256 * B];
            float xp2 = xgp[(size_t)512 * B];
            float xp3 = xgp[(size_t)768 * B];

            if (t >= 1) waitq(&g_done0q[t - 1][ks], 32);
            if (t >= 4) {
                waitq(&g_done1q[t - 4][0], 64); waitq(&g_done1q[t - 4][1], 64);
                waitq(&g_done1q[t - 4][2], 64); waitq(&g_done1q[t - 4][3], 64);
            }

            const float* hb = g_h0buf[(t + 3) & 3] + b0;
            ull acc0[4], acc1[4];
#pragma unroll
            for (int c = 0; c < 4; c++) { acc0[c] = 0ULL; acc1[c] = 0ULL; }

            ulonglong2 hv[2][4];
#pragma unroll
            for (int kc = 0; kc < 4; kc++)
                hv[0][kc] = *(const ulonglong2*)(hb + (size_t)(kbase + kc) * B);
#pragma unroll
            for (int it = 0; it < 16; ++it) {
                const int cur = it & 1, nxt = cur ^ 1;
                if (it < 15) {
#pragma unroll
                    for (int kc = 0; kc < 4; kc++)
                        hv[nxt][kc] = *(const ulonglong2*)(hb + (size_t)(kbase + (it + 1) * 4 + kc) * B);
                }
                const ull* wb = w_s2 + kbase + it * 4;
#pragma unroll
                for (int cc = 0; cc < 4; cc++) {
                    const ull* wr = wb + (rbase + cc) * 256;
                    ulonglong2 w01 = *(const ulonglong2*)(wr);
                    ulonglong2 w23 = *(const ulonglong2*)(wr + 2);
                    FMA2(acc0[cc], hv[cur][0].x, w01.x); FMA2(acc1[cc], hv[cur][0].y, w01.x);
                    FMA2(acc0[cc], hv[cur][1].x, w01.y); FMA2(acc1[cc], hv[cur][1].y, w01.y);
                    FMA2(acc0[cc], hv[cur][2].x, w23.x); FMA2(acc1[cc], hv[cur][2].y, w23.x);
                    FMA2(acc0[cc], hv[cur][3].x, w23.y); FMA2(acc1[cc], hv[cur][3].y, w23.y);
                }
            }
#pragma unroll
            for (int cc = 0; cc < 4; cc++) {
                ulonglong2 v; v.x = acc0[cc]; v.y = acc1[cc];
                *(ulonglong2*)&red[ks * 512 + (rbase + cc) * 64 + b0] = v;
            }
            __syncthreads();

            {   // activation: one (b, jl) pair per thread
                int r0 = (0 * 2 + jl) * 64 + ab, r1 = (1 * 2 + jl) * 64 + ab;
                int r2 = (2 * 2 + jl) * 64 + ab, r3 = (3 * 2 + jl) * 64 + ab;
                float s0 = xp0 + red[r0] + red[512 + r0] + red[1024 + r0] + red[1536 + r0];
                float s1 = xp1 + red[r1] + red[512 + r1] + red[1024 + r1] + red[1536 + r1];
                float s2 = xp2 + red[r2] + red[512 + r2] + red[1024 + r2] + red[1536 + r2];
                float s3 = xp3 + red[r3] + red[512 + r3] + red[1024 + r3] + red[1536 + r3];
                c_reg = sigf(s1) * c_reg + sigf(s0) * tanh_f(s2);
                float hval = sigf(s3) * tanh_f(c_reg);
                g_h0buf[t & 3][(j0 + jl) * B + ab] = hval;
            }
            __syncthreads();
            if (tid == 0) { __threadfence(); atomicAdd(&g_done0q[t][q0], 1); }
        }
    } else {
        // ========== layer 1 : 1 j -> 4 rows (r = g), K=512 ===================
        const int j = bid - NB_L0, q1 = j >> 6;
        for (int i = tid; i < 2048; i += 128) {
            int r = i >> 9, k = i & 511;
            float w = (k < 256) ? Wih1[(size_t)(r * 256 + j) * H + k]
                                : Whh1[(size_t)(r * 256 + j) * H + (k - 256)];
            w_s2[i] = dup2(w);
        }
        const int bg = tid & 15, ks = tid >> 4;   // ks in [0,8)
        const int b0 = bg * 4;
        float bi0 = 0.f, bi1 = 0.f, bi2 = 0.f, bi3 = 0.f;
        if (tid < 64) {
            bi0 = bih1[0 * 256 + j] + bhh1[0 * 256 + j];
            bi1 = bih1[1 * 256 + j] + bhh1[1 * 256 + j];
            bi2 = bih1[2 * 256 + j] + bhh1[2 * 256 + j];
            bi3 = bih1[3 * 256 + j] + bhh1[3 * 256 + j];
        }
        float c_reg = 0.f;
        __syncthreads();

        for (int tp = 0; tp < T; ++tp) {
            if (ks < 4) {
                waitq(&g_done0q[tp][ks], 32);
            } else if (tp >= 1) {
                waitq(&g_done1q[tp - 1][ks - 4], 64);
            }

            const float* hb = ((ks < 4) ? g_h0buf[tp & 3] : g_h1buf[(tp + 3) & 3]) + b0;
            const int kloc = (ks & 3) * 64;
            ull acc0[4], acc1[4];
#pragma unroll
            for (int c = 0; c < 4; c++) { acc0[c] = 0ULL; acc1[c] = 0ULL; }

            ulonglong2 hv[2][4];
#pragma unroll
            for (int kc = 0; kc < 4; kc++)
                hv[0][kc] = *(const ulonglong2*)(hb + (size_t)(kloc + kc) * B);
#pragma unroll
            for (int it = 0; it < 16; ++it) {
                const int cur = it & 1, nxt = cur ^ 1;
                if (it < 15) {
#pragma unroll
                    for (int kc = 0; kc < 4; kc++)
                        hv[nxt][kc] = *(const ulonglong2*)(hb + (size_t)(kloc + (it + 1) * 4 + kc) * B);
                }
                const ull* wb = w_s2 + ks * 64 + it * 4;
#pragma unroll
                for (int cc = 0; cc < 4; cc++) {
                    const ull* wr = wb + cc * 512;
                    ulonglong2 w01 = *(const ulonglong2*)(wr);
                    ulonglong2 w23 = *(const ulonglong2*)(wr + 2);
                    FMA2(acc0[cc], hv[cur][0].x, w01.x); FMA2(acc1[cc], hv[cur][0].y, w01.x);
                    FMA2(acc0[cc], hv[cur][1].x, w01.y); FMA2(acc1[cc], hv[cur][1].y, w01.y);
                    FMA2(acc0[cc], hv[cur][2].x, w23.x); FMA2(acc1[cc], hv[cur][2].y, w23.x);
                    FMA2(acc0[cc], hv[cur][3].x, w23.y); FMA2(acc1[cc], hv[cur][3].y, w23.y);
                }
            }
#pragma unroll
            for (int cc = 0; cc < 4; cc++) {
                ulonglong2 v; v.x = acc0[cc]; v.y = acc1[cc];
                *(ulonglong2*)&red[ks * 256 + cc * 64 + b0] = v;
            }
            __syncthreads();

            if (tid < 64) {
                int b = tid;
                float s0 = bi0, s1 = bi1, s2 = bi2, s3 = bi3;
#pragma unroll
                for (int q = 0; q < 8; q++) {
                    const float* rp = red + q * 256 + b;
                    s0 += rp[0]; s1 += rp[64]; s2 += rp[128]; s3 += rp[192];
                }
                c_reg = sigf(s1) * c_reg + sigf(s0) * tanh_f(s2);
                float hval = sigf(s3) * tanh_f(c_reg);
                g_h1buf[tp & 3][j * B + b] = hval;
                g_h1all[((size_t)tp * H + j) * B + b] = hval;
            }
            __syncthreads();
            if (tid == 0) { __threadfence(); atomicAdd(&g_done1q[tp][q1], 1); }
        }
    }
}

// ------- FC: logits[m][o] = h1[m] . fcW[o] + fcb ; A = g_h1all[t][k][b] ------
__global__ void __launch_bounds__(256) gemm_fc(const float* __restrict__ fcW,
                                               const float* __restrict__ fcb) {
    __shared__ float As[32][132];
    __shared__ float Bs[32][68];
    const int tid = threadIdx.x;
    const int tx = tid & 15, ty = tid >> 4;
    const size_t m0 = (size_t)blockIdx.x * 128;
    const int t0 = (int)(m0 >> 6);

    float acc[8][4];
#pragma unroll
    for (int i = 0; i < 8; i++)
#pragma unroll
        for (int j = 0; j < 4; j++) acc[i][j] = 0.f;

    for (int kc = 0; kc < H; kc += 32) {
        for (int i = tid; i < 32 * 128; i += 256) {
            int k = i >> 7, mm = i & 127;
            int tq = t0 + (mm >> 6), b = mm & 63;
            As[k][mm] = g_h1all[(size_t)tq * (H * B) + (size_t)(kc + k) * B + b];
        }
        for (int i = tid; i < 64 * 32; i += 256) {
            int nn = i >> 5, k = i & 31;
            Bs[k][nn] = fcW[(size_t)nn * H + kc + k];
        }
        __syncthreads();
#pragma unroll
        for (int k = 0; k < 32; k++) {
            float a[8], bb[4];
#pragma unroll
            for (int i = 0; i < 8; i++) a[i] = As[k][ty * 8 + i];
#pragma unroll
            for (int j = 0; j < 4; j++) bb[j] = Bs[k][tx * 4 + j];
#pragma unroll
            for (int i = 0; i < 8; i++)
#pragma unroll
                for (int j = 0; j < 4; j++) acc[i][j] += a[i] * bb[j];
        }
        __syncthreads();
    }
#pragma unroll
    for (int i = 0; i < 8; i++) {
        size_t row = (m0 + ty * 8 + i) * OUTN + tx * 4;
#pragma unroll
        for (int j = 0; j < 4; j++)
            g_logits[row + j] = acc[i][j] + fcb[tx * 4 + j];
    }
}

// ---------------- softmax over 64, remap [t][b] -> out[b][t] -----------------
__global__ void softmax_kernel(float* __restrict__ out) {
    const int tid = threadIdx.x;
    const int lane = tid & 31, w = tid >> 5;
    size_t row = (size_t)blockIdx.x * 8 + w;   // row = t*64 + b
    const float* L = g_logits + row * OUTN;
    float v0 = L[lane], v1 = L[lane + 32];
    float mx = fmaxf(v0, v1);
#pragma unroll
    for (int off = 16; off; off >>= 1) mx = fmaxf(mx, __shfl_xor_sync(~0u, mx, off));
    float e0 = expf(v0 - mx), e1 = expf(v1 - mx);
    float s = e0 + e1;
#pragma unroll
    for (int off = 16; off; off >>= 1) s += __shfl_xor_sync(~0u, s, off);
    float inv = 1.f / s;
    int t = (int)(row >> 6), b = (int)(row & 63);
    float* O = out + ((size_t)b * T + t) * OUTN;
    O[lane]      = e0 * inv;
    O[lane + 32] = e1 * inv;
}

// ---------------- launch ------------------------------------------------------
extern "C" void kernel_launch(void* const* d_in, const int* in_sizes, int n_in,
                              void* d_out, int out_size) {
    const int*   x     = (const int*)d_in[0];
    const float* table = (const float*)d_in[1];
    const float* Wih0  = (const float*)d_in[2];
    const float* Whh0  = (const float*)d_in[3];
    const float* bih0  = (const float*)d_in[4];
    const float* bhh0  = (const float*)d_in[5];
    const float* Wih1  = (const float*)d_in[6];
    const float* Whh1  = (const float*)d_in[7];
    const float* bih1  = (const float*)d_in[8];
    const float* bhh1  = (const float*)d_in[9];
    const float* fcW   = (const float*)d_in[10];
    const float* fcb   = (const float*)d_in[11];
    float* out = (float*)d_out;

    // reset counters + zero-state ring buffers every launch (graph-capturable)
    void *p0, *p1, *ph0, *ph1;
    cudaGetSymbolAddress(&p0,  g_done0q);
    cudaGetSymbolAddress(&p1,  g_done1q);
    cudaGetSymbolAddress(&ph0, g_h0buf);
    cudaGetSymbolAddress(&ph1, g_h1buf);
    cudaMemsetAsync(p0,  0, T * 4 * sizeof(int));
    cudaMemsetAsync(p1,  0, T * 4 * sizeof(int));
    cudaMemsetAsync(ph0, 0, 4 * H * B * sizeof(float));
    cudaMemsetAsync(ph1, 0, 4 * H * B * sizeof(float));

    prep_bias<<<4, 256>>>(bih0, bhh0);
    embed_kernel<<<(MROWS * D) / 256, 256>>>(x, table);
    gemm_xg0<<<dim3(8, MROWS / 128), 256>>>(Wih0);

    lstm_kernel<<<NBLK, 128>>>(Whh0, Wih1, Whh1, bih1, bhh1);

    gemm_fc<<<MROWS / 128, 256>>>(fcW, fcb);
    softmax_kernel<<<MROWS / 8, 256>>>(out);
}